// round 14
// baseline (speedup 1.0000x reference)
#include <cuda_runtime.h>
#include <cuda_bf16.h>
#include <cstdint>

#define NN 50000
#define DD 128
#define EE 800000
#define LL 3
#define BN_EPS_F 1e-5f
#define NSCAN ((NN + 255) / 256)   // 196
#define NTILE ((NN + 127) / 128)   // 391
#define PGRID 148                  // persistent grid

// Scratch (no allocations allowed)
__device__ float g_h[(size_t)NN * DD];     // ping-pong feature buf
__device__ float g_A[(size_t)NN * DD];     // combined (1+eps)h + agg
__device__ int   g_flag64;
__device__ int   g_cnt[NN];                // degree histogram (self-rezeroing)
__device__ int   g_cur[NN];                // fill cursor (init = rowptr)
__device__ int   g_rowptr[NN + 1];
__device__ int   g_col[EE];
__device__ int   g_bsum[NSCAN];

// ---------------------------------------------------------------------------
// smem layout for fused kernel: row-major bf16 tiles, 272 B row stride
// ---------------------------------------------------------------------------
#define ROWB    272
#define TILEB   (128 * ROWB)
#define OFF_AH  0
#define OFF_AL  (OFF_AH + TILEB)
#define OFF_W1H (OFF_AL + TILEB)
#define OFF_W1L (OFF_W1H + TILEB)
#define OFF_W2H (OFF_W1L + TILEB)
#define OFF_W2L (OFF_W2H + TILEB)
#define OFF_S   (OFF_W2L + TILEB)
#define OFF_T   (OFF_S + 512)
#define OFF_B2  (OFF_T + 512)
#define SMEM_TOTAL (OFF_B2 + 512)

__device__ __forceinline__ uint32_t smem_u32(const void* p) {
    uint32_t a;
    asm("{ .reg .u64 t; cvta.to.shared.u64 t, %1; cvt.u32.u64 %0, t; }" : "=r"(a) : "l"(p));
    return a;
}
__device__ __forceinline__ void ldsm4(uint32_t r[4], uint32_t a) {
    asm volatile("ldmatrix.sync.aligned.m8n8.x4.shared.b16 {%0,%1,%2,%3}, [%4];"
                 : "=r"(r[0]), "=r"(r[1]), "=r"(r[2]), "=r"(r[3]) : "r"(a));
}
__device__ __forceinline__ void ldsm4t(uint32_t r[4], uint32_t a) {
    asm volatile("ldmatrix.sync.aligned.m8n8.x4.trans.shared.b16 {%0,%1,%2,%3}, [%4];"
                 : "=r"(r[0]), "=r"(r[1]), "=r"(r[2]), "=r"(r[3]) : "r"(a));
}
__device__ __forceinline__ void mma_bf16(float d[4], const uint32_t a[4], const uint32_t* b) {
    asm volatile("mma.sync.aligned.m16n8k16.row.col.f32.bf16.bf16.f32 "
                 "{%0,%1,%2,%3}, {%4,%5,%6,%7}, {%8,%9}, {%0,%1,%2,%3};"
                 : "+f"(d[0]), "+f"(d[1]), "+f"(d[2]), "+f"(d[3])
                 : "r"(a[0]), "r"(a[1]), "r"(a[2]), "r"(a[3]), "r"(b[0]), "r"(b[1]));
}
__device__ __forceinline__ uint32_t b2u(__nv_bfloat162 v) {
    return *reinterpret_cast<uint32_t*>(&v);
}
__device__ __forceinline__ void split_pair(float x, float y, uint32_t& hi, uint32_t& lo) {
    __nv_bfloat16 hx = __float2bfloat16(x);
    __nv_bfloat16 hy = __float2bfloat16(y);
    hi = b2u(__halves2bfloat162(hx, hy));
    lo = b2u(__floats2bfloat162_rn(x - __bfloat162float(hx), y - __bfloat162float(hy)));
}

// ---------------------------------------------------------------------------
// CSR gather: A[i] = (1+eps)*h[i] + sum_{j in nbr(i)} h[j]
// warp-per-row; lane owns 4 columns (one float4). MLP=8 this round.
// ---------------------------------------------------------------------------
__global__ void __launch_bounds__(256) gather_kernel(
    const float* __restrict__ hin,
    const float* __restrict__ eps, int layer,
    float* __restrict__ A)
{
    const int row = (blockIdx.x * blockDim.x + threadIdx.x) >> 5;
    if (row >= NN) return;
    const int lane = threadIdx.x & 31;
    const float ev = 1.0f + eps[layer];

    const int p0 = g_rowptr[row], p1 = g_rowptr[row + 1];
    float4 acc = make_float4(0.f, 0.f, 0.f, 0.f);

    for (int pb = p0; pb < p1; pb += 32) {
        const int nload = min(32, p1 - pb);
        int myidx = (pb + lane < p1) ? g_col[pb + lane] : 0;
        int j = 0;
        for (; j + 8 <= nload; j += 8) {
            float4 v[8];
#pragma unroll
            for (int u = 0; u < 8; u++) {
                int s = __shfl_sync(0xffffffffu, myidx, j + u);
                v[u] = *(const float4*)(hin + (size_t)s * DD + lane * 4);
            }
#pragma unroll
            for (int u = 0; u < 8; u++) {
                acc.x += v[u].x; acc.y += v[u].y;
                acc.z += v[u].z; acc.w += v[u].w;
            }
        }
        for (; j + 4 <= nload; j += 4) {
            float4 v[4];
#pragma unroll
            for (int u = 0; u < 4; u++) {
                int s = __shfl_sync(0xffffffffu, myidx, j + u);
                v[u] = *(const float4*)(hin + (size_t)s * DD + lane * 4);
            }
#pragma unroll
            for (int u = 0; u < 4; u++) {
                acc.x += v[u].x; acc.y += v[u].y;
                acc.z += v[u].z; acc.w += v[u].w;
            }
        }
        for (; j < nload; j++) {
            int s = __shfl_sync(0xffffffffu, myidx, j);
            float4 v = *(const float4*)(hin + (size_t)s * DD + lane * 4);
            acc.x += v.x; acc.y += v.y; acc.z += v.z; acc.w += v.w;
        }
    }
    const float4 hv = *(const float4*)(hin + (size_t)row * DD + lane * 4);
    acc.x = fmaf(ev, hv.x, acc.x);
    acc.y = fmaf(ev, hv.y, acc.y);
    acc.z = fmaf(ev, hv.z, acc.z);
    acc.w = fmaf(ev, hv.w, acc.w);
    *(float4*)(A + (size_t)row * DD + lane * 4) = acc;
}

// ---------------------------------------------------------------------------
// Persistent fused MLP (R12-proven, unchanged)
// ---------------------------------------------------------------------------
template <int RELU2>
__global__ void __launch_bounds__(256, 1) fused_layer_kernel(
    const float* __restrict__ Ain,
    const float* __restrict__ W1, const float* __restrict__ b1,
    const float* __restrict__ gamma, const float* __restrict__ beta,
    const float* __restrict__ mean, const float* __restrict__ var,
    const float* __restrict__ W2, const float* __restrict__ b2,
    float* __restrict__ out)
{
    extern __shared__ __align__(128) char smem[];
    const uint32_t sb = smem_u32(smem);
    const int tid = threadIdx.x, lane = tid & 31, wid = tid >> 5;
    const int wm = wid & 3, wn = wid >> 2;
    const int m0 = wm * 32, n0 = wn * 64;

    if (tid < 128) {
        float sc = gamma[tid] * rsqrtf(var[tid] + BN_EPS_F);
        *(float*)(smem + OFF_S + tid * 4) = sc;
        *(float*)(smem + OFF_T + tid * 4) = (b1[tid] - mean[tid]) * sc + beta[tid];
        *(float*)(smem + OFF_B2 + tid * 4) = b2[tid];
    }
#pragma unroll
    for (int w = 0; w < 2; w++) {
        const float* Wsrc = w ? W2 : W1;
        const int ho = w ? OFF_W2H : OFF_W1H;
        const int lo = w ? OFF_W2L : OFF_W1L;
#pragma unroll
        for (int it = 0; it < 16; it++) {
            int q = tid + it * 256;
            int k = q >> 5, c4 = (q & 31) << 2;
            float4 v = *(const float4*)(Wsrc + (size_t)k * DD + c4);
            uint2 hh, ll;
            split_pair(v.x, v.y, hh.x, ll.x);
            split_pair(v.z, v.w, hh.y, ll.y);
            uint32_t o = (uint32_t)k * ROWB + (uint32_t)c4 * 2;
            *(uint2*)(smem + ho + o) = hh;
            *(uint2*)(smem + lo + o) = ll;
        }
    }

    const uint32_t aRowOff = (uint32_t)(m0 + (lane & 15)) * ROWB + (uint32_t)(lane >> 4) * 16;
    const uint32_t bRowOff = (uint32_t)(lane & 15) * ROWB + (uint32_t)(n0 + ((lane >> 4) << 3)) * 2;

    float d[2][8][4];

#define RUN_GEMM(AOFF_H, AOFF_L, WOFF_H, WOFF_L)                                \
    {                                                                           \
        _Pragma("unroll")                                                       \
        for (int mt = 0; mt < 2; mt++)                                          \
            _Pragma("unroll")                                                   \
            for (int nt = 0; nt < 8; nt++)                                      \
                _Pragma("unroll")                                               \
                for (int e = 0; e < 4; e++) d[mt][nt][e] = 0.f;                 \
        const uint32_t aH = sb + AOFF_H + aRowOff;                              \
        const uint32_t aL = sb + AOFF_L + aRowOff;                              \
        const uint32_t bH = sb + WOFF_H + bRowOff;                              \
        const uint32_t bL = sb + WOFF_L + bRowOff;                              \
        _Pragma("unroll")                                                       \
        for (int kk = 0; kk < 8; kk++) {                                        \
            uint32_t ah[2][4], al[2][4], bh[4][4], bl[4][4];                    \
            ldsm4(ah[0], aH + kk * 32);                                         \
            ldsm4(ah[1], aH + 16 * ROWB + kk * 32);                             \
            ldsm4(al[0], aL + kk * 32);                                         \
            ldsm4(al[1], aL + 16 * ROWB + kk * 32);                             \
            _Pragma("unroll")                                                   \
            for (int j = 0; j < 4; j++) {                                       \
                ldsm4t(bh[j], bH + (uint32_t)kk * 16 * ROWB + j * 32);          \
                ldsm4t(bl[j], bL + (uint32_t)kk * 16 * ROWB + j * 32);          \
            }                                                                   \
            _Pragma("unroll")                                                   \
            for (int mt = 0; mt < 2; mt++)                                      \
                _Pragma("unroll")                                               \
                for (int j = 0; j < 4; j++) {                                   \
                    mma_bf16(d[mt][2 * j],     ah[mt], &bh[j][0]);              \
                    mma_bf16(d[mt][2 * j + 1], ah[mt], &bh[j][2]);              \
                    mma_bf16(d[mt][2 * j],     ah[mt], &bl[j][0]);              \
                    mma_bf16(d[mt][2 * j + 1], ah[mt], &bl[j][2]);              \
                    mma_bf16(d[mt][2 * j],     al[mt], &bh[j][0]);              \
                    mma_bf16(d[mt][2 * j + 1], al[mt], &bh[j][2]);              \
                }                                                               \
        }                                                                       \
    }

    for (int tile = blockIdx.x; tile < NTILE; tile += PGRID) {
        const int row0 = tile * 128;
        __syncthreads();

#pragma unroll
        for (int it = 0; it < 16; it++) {
            int q = tid + it * 256;
            int m = q >> 5, c4 = (q & 31) << 2;
            int grow = row0 + m;
            float4 v = make_float4(0.f, 0.f, 0.f, 0.f);
            if (grow < NN) v = *(const float4*)(Ain + (size_t)grow * DD + c4);
            uint2 hh, ll;
            split_pair(v.x, v.y, hh.x, ll.x);
            split_pair(v.z, v.w, hh.y, ll.y);
            uint32_t o = (uint32_t)m * ROWB + (uint32_t)c4 * 2;
            *(uint2*)(smem + OFF_AH + o) = hh;
            *(uint2*)(smem + OFF_AL + o) = ll;
        }
        __syncthreads();

        RUN_GEMM(OFF_AH, OFF_AL, OFF_W1H, OFF_W1L);
        __syncthreads();

        {
            const int g = lane >> 2, tg = lane & 3;
#pragma unroll
            for (int mt = 0; mt < 2; mt++) {
#pragma unroll
                for (int nt = 0; nt < 8; nt++) {
                    int c = n0 + nt * 8 + tg * 2;
                    float s0 = *(const float*)(smem + OFF_S + c * 4);
                    float s1 = *(const float*)(smem + OFF_S + c * 4 + 4);
                    float t0 = *(const float*)(smem + OFF_T + c * 4);
                    float t1 = *(const float*)(smem + OFF_T + c * 4 + 4);
                    int r0 = m0 + mt * 16 + g, r1 = r0 + 8;
                    float z00 = fmaxf(d[mt][nt][0] * s0 + t0, 0.f);
                    float z01 = fmaxf(d[mt][nt][1] * s1 + t1, 0.f);
                    float z10 = fmaxf(d[mt][nt][2] * s0 + t0, 0.f);
                    float z11 = fmaxf(d[mt][nt][3] * s1 + t1, 0.f);
                    uint32_t hi, lo;
                    uint32_t o0 = (uint32_t)r0 * ROWB + (uint32_t)c * 2;
                    uint32_t o1 = (uint32_t)r1 * ROWB + (uint32_t)c * 2;
                    split_pair(z00, z01, hi, lo);
                    *(uint32_t*)(smem + OFF_AH + o0) = hi;
                    *(uint32_t*)(smem + OFF_AL + o0) = lo;
                    split_pair(z10, z11, hi, lo);
                    *(uint32_t*)(smem + OFF_AH + o1) = hi;
                    *(uint32_t*)(smem + OFF_AL + o1) = lo;
                }
            }
        }
        __syncthreads();

        RUN_GEMM(OFF_AH, OFF_AL, OFF_W2H, OFF_W2L);

        {
            const int g = lane >> 2, tg = lane & 3;
#pragma unroll
            for (int mt = 0; mt < 2; mt++) {
                int r0 = row0 + m0 + mt * 16 + g;
                int r1 = r0 + 8;
#pragma unroll
                for (int nt = 0; nt < 8; nt++) {
                    int c = n0 + nt * 8 + tg * 2;
                    float bb0 = *(const float*)(smem + OFF_B2 + c * 4);
                    float bb1 = *(const float*)(smem + OFF_B2 + c * 4 + 4);
                    float2 v0 = make_float2(d[mt][nt][0] + bb0, d[mt][nt][1] + bb1);
                    float2 v1 = make_float2(d[mt][nt][2] + bb0, d[mt][nt][3] + bb1);
                    if (RELU2) {
                        v0.x = fmaxf(v0.x, 0.f); v0.y = fmaxf(v0.y, 0.f);
                        v1.x = fmaxf(v1.x, 0.f); v1.y = fmaxf(v1.y, 0.f);
                    }
                    if (r0 < NN) *(float2*)(out + (size_t)r0 * DD + c) = v0;
                    if (r1 < NN) *(float2*)(out + (size_t)r1 * DD + c) = v1;
                }
            }
        }
    }
#undef RUN_GEMM
}

// ---------------------------------------------------------------------------
// CSR construction (R12-proven: detect -> hist -> scan_block -> add_off -> fill)
// ---------------------------------------------------------------------------
__global__ void detect_kernel(const long long* __restrict__ ei)
{
    const int lane = threadIdx.x & 31;
    int bad = 0;
#pragma unroll
    for (int c = 0; c < 32; c++) {
        long long v = ei[c * 32 + lane];
        bad |= (v < 0 || v >= NN);
    }
    unsigned m = __ballot_sync(0xffffffffu, bad);
    if (lane == 0) g_flag64 = (m == 0u);
}

__global__ void __launch_bounds__(256) hist_kernel(const void* __restrict__ ei_raw)
{
    unsigned e2 = (blockIdx.x * blockDim.x + threadIdx.x) * 2;
    if (e2 >= EE) return;
    int d0, d1;
    if (g_flag64) {
        const longlong2 v = *(const longlong2*)((const long long*)ei_raw + EE + e2);
        d0 = (int)v.x; d1 = (int)v.y;
    } else {
        const int2 v = *(const int2*)((const int*)ei_raw + EE + e2);
        d0 = v.x; d1 = v.y;
    }
    if ((unsigned)d0 < NN) atomicAdd(&g_cnt[d0], 1);
    if ((unsigned)d1 < NN) atomicAdd(&g_cnt[d1], 1);
}

__global__ void __launch_bounds__(256) scan_block_kernel()
{
    __shared__ int s[256];
    int i = blockIdx.x * 256 + threadIdx.x;
    int v = (i < NN) ? g_cnt[i] : 0;
    if (i < NN) g_cnt[i] = 0;       // re-zero for next call
    s[threadIdx.x] = v;
    __syncthreads();
#pragma unroll
    for (int off = 1; off < 256; off <<= 1) {
        int t = (threadIdx.x >= off) ? s[threadIdx.x - off] : 0;
        __syncthreads();
        if (threadIdx.x >= off) s[threadIdx.x] += t;
        __syncthreads();
    }
    if (i < NN) g_rowptr[i] = s[threadIdx.x] - v;
    if (threadIdx.x == 255) g_bsum[blockIdx.x] = s[255];
}

__global__ void __launch_bounds__(256) add_off_kernel()
{
    __shared__ int base_s;
    const int bid = blockIdx.x;
    if (threadIdx.x < 32) {
        int s = 0;
        for (int i = threadIdx.x; i < bid; i += 32) s += g_bsum[i];
#pragma unroll
        for (int off = 16; off; off >>= 1)
            s += __shfl_down_sync(0xffffffffu, s, off);
        if (threadIdx.x == 0) base_s = s;
    }
    __syncthreads();
    int i = bid * 256 + threadIdx.x;
    if (i < NN) {
        int rp = g_rowptr[i] + base_s;
        g_rowptr[i] = rp;
        g_cur[i] = rp;
    }
    if (i == 0) g_rowptr[NN] = EE;
}

__global__ void __launch_bounds__(256) fill_kernel(const void* __restrict__ ei_raw)
{
    unsigned e2 = (blockIdx.x * blockDim.x + threadIdx.x) * 2;
    if (e2 >= EE) return;
    int s0, s1, d0, d1;
    if (g_flag64) {
        const longlong2 sv = *(const longlong2*)((const long long*)ei_raw + e2);
        const longlong2 dv = *(const longlong2*)((const long long*)ei_raw + EE + e2);
        s0 = (int)sv.x; s1 = (int)sv.y;
        d0 = (int)dv.x; d1 = (int)dv.y;
    } else {
        const int2 sv = *(const int2*)((const int*)ei_raw + e2);
        const int2 dv = *(const int2*)((const int*)ei_raw + EE + e2);
        s0 = sv.x; s1 = sv.y;
        d0 = dv.x; d1 = dv.y;
    }
    if ((unsigned)d0 < NN && (unsigned)s0 < NN)
        g_col[atomicAdd(&g_cur[d0], 1)] = s0;
    if ((unsigned)d1 < NN && (unsigned)s1 < NN)
        g_col[atomicAdd(&g_cur[d1], 1)] = s1;
}

// ---------------------------------------------------------------------------
// Launcher
// ---------------------------------------------------------------------------
extern "C" void kernel_launch(void* const* d_in, const int* in_sizes, int n_in,
                              void* d_out, int out_size)
{
    const float* x   = (const float*)d_in[0];
    const void*  ei  = d_in[1];
    const float* W1  = (const float*)d_in[2];
    const float* b1  = (const float*)d_in[3];
    const float* gam = (const float*)d_in[4];
    const float* bet = (const float*)d_in[5];
    const float* bmu = (const float*)d_in[6];
    const float* bva = (const float*)d_in[7];
    const float* W2  = (const float*)d_in[8];
    const float* b2  = (const float*)d_in[9];
    const float* eps = (const float*)d_in[10];
    float*       out = (float*)d_out;

    float* hbuf;
    cudaGetSymbolAddress((void**)&hbuf, g_h);
    float* Abuf;
    cudaGetSymbolAddress((void**)&Abuf, g_A);

    cudaFuncSetAttribute(fused_layer_kernel<1>, cudaFuncAttributeMaxDynamicSharedMemorySize, SMEM_TOTAL);
    cudaFuncSetAttribute(fused_layer_kernel<0>, cudaFuncAttributeMaxDynamicSharedMemorySize, SMEM_TOTAL);

    const int eb2 = (EE / 2 + 255) / 256;          // 1563 (2 edges/thread)
    const int gat_blocks = (NN * 32 + 255) / 256;  // warp per row

    // ---- CSR build (5 launches, R12-proven) ----
    detect_kernel<<<1, 32>>>((const long long*)ei);
    hist_kernel<<<eb2, 256>>>(ei);
    scan_block_kernel<<<NSCAN, 256>>>();
    add_off_kernel<<<NSCAN, 256>>>();
    fill_kernel<<<eb2, 256>>>(ei);

    // ---- 3 layers: gather -> persistent fused MLP ----
    const float* hin = x;
    for (int l = 0; l < LL; ++l) {
        float* hout = (l == LL - 1) ? out : hbuf;

        gather_kernel<<<gat_blocks, 256>>>(hin, eps, l, Abuf);

        if (l < LL - 1) {
            fused_layer_kernel<1><<<PGRID, 256, SMEM_TOTAL>>>(
                Abuf,
                W1 + (size_t)l * DD * DD, b1 + (size_t)l * DD,
                gam + (size_t)l * DD, bet + (size_t)l * DD,
                bmu + (size_t)l * DD, bva + (size_t)l * DD,
                W2 + (size_t)l * DD * DD, b2 + (size_t)l * DD,
                hout);
        } else {
            fused_layer_kernel<0><<<PGRID, 256, SMEM_TOTAL>>>(
                Abuf,
                W1 + (size_t)l * DD * DD, b1 + (size_t)l * DD,
                gam + (size_t)l * DD, bet + (size_t)l * DD,
                bmu + (size_t)l * DD, bva + (size_t)l * DD,
                W2 + (size_t)l * DD * DD, b2 + (size_t)l * DD,
                hout);
        }
        hin = hout;
    }
}

// round 15
// speedup vs baseline: 1.0771x; 1.0771x over previous
#include <cuda_runtime.h>
#include <cuda_bf16.h>
#include <cstdint>

#define NN 50000
#define DD 128
#define EE 800000
#define LL 3
#define BN_EPS_F 1e-5f
#define NSCAN ((NN + 255) / 256)   // 196
#define NTILE ((NN + 127) / 128)   // 391
#define PGRID 148                  // persistent grid

// Scratch (no allocations allowed)
__device__ float g_h[(size_t)NN * DD];     // ping-pong feature buf
__device__ float g_A[(size_t)NN * DD];     // combined (1+eps)h + agg
__device__ int   g_flag64;
__device__ int   g_cnt[NN];                // degree histogram (self-rezeroing)
__device__ int   g_cur[NN];                // fill cursor (init = rowptr)
__device__ int   g_rowptr[NN + 1];
__device__ int   g_col[EE];
__device__ int   g_bsum[NSCAN];

// ---------------------------------------------------------------------------
// smem layout for fused kernel: row-major bf16 tiles, 272 B row stride
// ---------------------------------------------------------------------------
#define ROWB    272
#define TILEB   (128 * ROWB)
#define OFF_AH  0
#define OFF_AL  (OFF_AH + TILEB)
#define OFF_W1H (OFF_AL + TILEB)
#define OFF_W1L (OFF_W1H + TILEB)
#define OFF_W2H (OFF_W1L + TILEB)
#define OFF_W2L (OFF_W2H + TILEB)
#define OFF_S   (OFF_W2L + TILEB)
#define OFF_T   (OFF_S + 512)
#define OFF_B2  (OFF_T + 512)
#define SMEM_TOTAL (OFF_B2 + 512)

__device__ __forceinline__ uint32_t smem_u32(const void* p) {
    uint32_t a;
    asm("{ .reg .u64 t; cvta.to.shared.u64 t, %1; cvt.u32.u64 %0, t; }" : "=r"(a) : "l"(p));
    return a;
}
__device__ __forceinline__ void ldsm4(uint32_t r[4], uint32_t a) {
    asm volatile("ldmatrix.sync.aligned.m8n8.x4.shared.b16 {%0,%1,%2,%3}, [%4];"
                 : "=r"(r[0]), "=r"(r[1]), "=r"(r[2]), "=r"(r[3]) : "r"(a));
}
__device__ __forceinline__ void ldsm4t(uint32_t r[4], uint32_t a) {
    asm volatile("ldmatrix.sync.aligned.m8n8.x4.trans.shared.b16 {%0,%1,%2,%3}, [%4];"
                 : "=r"(r[0]), "=r"(r[1]), "=r"(r[2]), "=r"(r[3]) : "r"(a));
}
__device__ __forceinline__ void mma_bf16(float d[4], const uint32_t a[4], const uint32_t* b) {
    asm volatile("mma.sync.aligned.m16n8k16.row.col.f32.bf16.bf16.f32 "
                 "{%0,%1,%2,%3}, {%4,%5,%6,%7}, {%8,%9}, {%0,%1,%2,%3};"
                 : "+f"(d[0]), "+f"(d[1]), "+f"(d[2]), "+f"(d[3])
                 : "r"(a[0]), "r"(a[1]), "r"(a[2]), "r"(a[3]), "r"(b[0]), "r"(b[1]));
}
__device__ __forceinline__ uint32_t b2u(__nv_bfloat162 v) {
    return *reinterpret_cast<uint32_t*>(&v);
}
__device__ __forceinline__ void split_pair(float x, float y, uint32_t& hi, uint32_t& lo) {
    __nv_bfloat16 hx = __float2bfloat16(x);
    __nv_bfloat16 hy = __float2bfloat16(y);
    hi = b2u(__halves2bfloat162(hx, hy));
    lo = b2u(__floats2bfloat162_rn(x - __bfloat162float(hx), y - __bfloat162float(hy)));
}

// ---------------------------------------------------------------------------
// CSR gather (proven optimum): A[i] = (1+eps)*h[i] + sum_{j in nbr(i)} h[j]
// warp-per-row; lane owns 4 columns (one float4). MLP=4.
// ---------------------------------------------------------------------------
__global__ void __launch_bounds__(256) gather_kernel(
    const float* __restrict__ hin,
    const float* __restrict__ eps, int layer,
    float* __restrict__ A)
{
    const int row = (blockIdx.x * blockDim.x + threadIdx.x) >> 5;
    if (row >= NN) return;
    const int lane = threadIdx.x & 31;
    const float ev = 1.0f + eps[layer];

    const int p0 = g_rowptr[row], p1 = g_rowptr[row + 1];
    float4 acc = make_float4(0.f, 0.f, 0.f, 0.f);

    for (int pb = p0; pb < p1; pb += 32) {
        const int nload = min(32, p1 - pb);
        int myidx = (pb + lane < p1) ? g_col[pb + lane] : 0;
        int j = 0;
        for (; j + 4 <= nload; j += 4) {
            int s0 = __shfl_sync(0xffffffffu, myidx, j + 0);
            int s1 = __shfl_sync(0xffffffffu, myidx, j + 1);
            int s2 = __shfl_sync(0xffffffffu, myidx, j + 2);
            int s3 = __shfl_sync(0xffffffffu, myidx, j + 3);
            float4 v0 = *(const float4*)(hin + (size_t)s0 * DD + lane * 4);
            float4 v1 = *(const float4*)(hin + (size_t)s1 * DD + lane * 4);
            float4 v2 = *(const float4*)(hin + (size_t)s2 * DD + lane * 4);
            float4 v3 = *(const float4*)(hin + (size_t)s3 * DD + lane * 4);
            acc.x += v0.x + v1.x + v2.x + v3.x;
            acc.y += v0.y + v1.y + v2.y + v3.y;
            acc.z += v0.z + v1.z + v2.z + v3.z;
            acc.w += v0.w + v1.w + v2.w + v3.w;
        }
        for (; j < nload; j++) {
            int s = __shfl_sync(0xffffffffu, myidx, j);
            float4 v = *(const float4*)(hin + (size_t)s * DD + lane * 4);
            acc.x += v.x; acc.y += v.y; acc.z += v.z; acc.w += v.w;
        }
    }
    const float4 hv = *(const float4*)(hin + (size_t)row * DD + lane * 4);
    acc.x = fmaf(ev, hv.x, acc.x);
    acc.y = fmaf(ev, hv.y, acc.y);
    acc.z = fmaf(ev, hv.z, acc.z);
    acc.w = fmaf(ev, hv.w, acc.w);
    *(float4*)(A + (size_t)row * DD + lane * 4) = acc;
}

// ---------------------------------------------------------------------------
// Persistent fused MLP (R12-proven):
//   out = [relu]( relu(BN(A @ W1 + b1)) @ W2 + b2 )
// ---------------------------------------------------------------------------
template <int RELU2>
__global__ void __launch_bounds__(256, 1) fused_layer_kernel(
    const float* __restrict__ Ain,
    const float* __restrict__ W1, const float* __restrict__ b1,
    const float* __restrict__ gamma, const float* __restrict__ beta,
    const float* __restrict__ mean, const float* __restrict__ var,
    const float* __restrict__ W2, const float* __restrict__ b2,
    float* __restrict__ out)
{
    extern __shared__ __align__(128) char smem[];
    const uint32_t sb = smem_u32(smem);
    const int tid = threadIdx.x, lane = tid & 31, wid = tid >> 5;
    const int wm = wid & 3, wn = wid >> 2;
    const int m0 = wm * 32, n0 = wn * 64;

    if (tid < 128) {
        float sc = gamma[tid] * rsqrtf(var[tid] + BN_EPS_F);
        *(float*)(smem + OFF_S + tid * 4) = sc;
        *(float*)(smem + OFF_T + tid * 4) = (b1[tid] - mean[tid]) * sc + beta[tid];
        *(float*)(smem + OFF_B2 + tid * 4) = b2[tid];
    }
#pragma unroll
    for (int w = 0; w < 2; w++) {
        const float* Wsrc = w ? W2 : W1;
        const int ho = w ? OFF_W2H : OFF_W1H;
        const int lo = w ? OFF_W2L : OFF_W1L;
#pragma unroll
        for (int it = 0; it < 16; it++) {
            int q = tid + it * 256;
            int k = q >> 5, c4 = (q & 31) << 2;
            float4 v = *(const float4*)(Wsrc + (size_t)k * DD + c4);
            uint2 hh, ll;
            split_pair(v.x, v.y, hh.x, ll.x);
            split_pair(v.z, v.w, hh.y, ll.y);
            uint32_t o = (uint32_t)k * ROWB + (uint32_t)c4 * 2;
            *(uint2*)(smem + ho + o) = hh;
            *(uint2*)(smem + lo + o) = ll;
        }
    }

    const uint32_t aRowOff = (uint32_t)(m0 + (lane & 15)) * ROWB + (uint32_t)(lane >> 4) * 16;
    const uint32_t bRowOff = (uint32_t)(lane & 15) * ROWB + (uint32_t)(n0 + ((lane >> 4) << 3)) * 2;

    float d[2][8][4];

#define RUN_GEMM(AOFF_H, AOFF_L, WOFF_H, WOFF_L)                                \
    {                                                                           \
        _Pragma("unroll")                                                       \
        for (int mt = 0; mt < 2; mt++)                                          \
            _Pragma("unroll")                                                   \
            for (int nt = 0; nt < 8; nt++)                                      \
                _Pragma("unroll")                                               \
                for (int e = 0; e < 4; e++) d[mt][nt][e] = 0.f;                 \
        const uint32_t aH = sb + AOFF_H + aRowOff;                              \
        const uint32_t aL = sb + AOFF_L + aRowOff;                              \
        const uint32_t bH = sb + WOFF_H + bRowOff;                              \
        const uint32_t bL = sb + WOFF_L + bRowOff;                              \
        _Pragma("unroll")                                                       \
        for (int kk = 0; kk < 8; kk++) {                                        \
            uint32_t ah[2][4], al[2][4], bh[4][4], bl[4][4];                    \
            ldsm4(ah[0], aH + kk * 32);                                         \
            ldsm4(ah[1], aH + 16 * ROWB + kk * 32);                             \
            ldsm4(al[0], aL + kk * 32);                                         \
            ldsm4(al[1], aL + 16 * ROWB + kk * 32);                             \
            _Pragma("unroll")                                                   \
            for (int j = 0; j < 4; j++) {                                       \
                ldsm4t(bh[j], bH + (uint32_t)kk * 16 * ROWB + j * 32);          \
                ldsm4t(bl[j], bL + (uint32_t)kk * 16 * ROWB + j * 32);          \
            }                                                                   \
            _Pragma("unroll")                                                   \
            for (int mt = 0; mt < 2; mt++)                                      \
                _Pragma("unroll")                                               \
                for (int j = 0; j < 4; j++) {                                   \
                    mma_bf16(d[mt][2 * j],     ah[mt], &bh[j][0]);              \
                    mma_bf16(d[mt][2 * j + 1], ah[mt], &bh[j][2]);              \
                    mma_bf16(d[mt][2 * j],     ah[mt], &bl[j][0]);              \
                    mma_bf16(d[mt][2 * j + 1], ah[mt], &bl[j][2]);              \
                    mma_bf16(d[mt][2 * j],     al[mt], &bh[j][0]);              \
                    mma_bf16(d[mt][2 * j + 1], al[mt], &bh[j][2]);              \
                }                                                               \
        }                                                                       \
    }

    for (int tile = blockIdx.x; tile < NTILE; tile += PGRID) {
        const int row0 = tile * 128;
        __syncthreads();

#pragma unroll
        for (int it = 0; it < 16; it++) {
            int q = tid + it * 256;
            int m = q >> 5, c4 = (q & 31) << 2;
            int grow = row0 + m;
            float4 v = make_float4(0.f, 0.f, 0.f, 0.f);
            if (grow < NN) v = *(const float4*)(Ain + (size_t)grow * DD + c4);
            uint2 hh, ll;
            split_pair(v.x, v.y, hh.x, ll.x);
            split_pair(v.z, v.w, hh.y, ll.y);
            uint32_t o = (uint32_t)m * ROWB + (uint32_t)c4 * 2;
            *(uint2*)(smem + OFF_AH + o) = hh;
            *(uint2*)(smem + OFF_AL + o) = ll;
        }
        __syncthreads();

        RUN_GEMM(OFF_AH, OFF_AL, OFF_W1H, OFF_W1L);
        __syncthreads();

        {
            const int g = lane >> 2, tg = lane & 3;
#pragma unroll
            for (int mt = 0; mt < 2; mt++) {
#pragma unroll
                for (int nt = 0; nt < 8; nt++) {
                    int c = n0 + nt * 8 + tg * 2;
                    float s0 = *(const float*)(smem + OFF_S + c * 4);
                    float s1 = *(const float*)(smem + OFF_S + c * 4 + 4);
                    float t0 = *(const float*)(smem + OFF_T + c * 4);
                    float t1 = *(const float*)(smem + OFF_T + c * 4 + 4);
                    int r0 = m0 + mt * 16 + g, r1 = r0 + 8;
                    float z00 = fmaxf(d[mt][nt][0] * s0 + t0, 0.f);
                    float z01 = fmaxf(d[mt][nt][1] * s1 + t1, 0.f);
                    float z10 = fmaxf(d[mt][nt][2] * s0 + t0, 0.f);
                    float z11 = fmaxf(d[mt][nt][3] * s1 + t1, 0.f);
                    uint32_t hi, lo;
                    uint32_t o0 = (uint32_t)r0 * ROWB + (uint32_t)c * 2;
                    uint32_t o1 = (uint32_t)r1 * ROWB + (uint32_t)c * 2;
                    split_pair(z00, z01, hi, lo);
                    *(uint32_t*)(smem + OFF_AH + o0) = hi;
                    *(uint32_t*)(smem + OFF_AL + o0) = lo;
                    split_pair(z10, z11, hi, lo);
                    *(uint32_t*)(smem + OFF_AH + o1) = hi;
                    *(uint32_t*)(smem + OFF_AL + o1) = lo;
                }
            }
        }
        __syncthreads();

        RUN_GEMM(OFF_AH, OFF_AL, OFF_W2H, OFF_W2L);

        {
            const int g = lane >> 2, tg = lane & 3;
#pragma unroll
            for (int mt = 0; mt < 2; mt++) {
                int r0 = row0 + m0 + mt * 16 + g;
                int r1 = r0 + 8;
#pragma unroll
                for (int nt = 0; nt < 8; nt++) {
                    int c = n0 + nt * 8 + tg * 2;
                    float bb0 = *(const float*)(smem + OFF_B2 + c * 4);
                    float bb1 = *(const float*)(smem + OFF_B2 + c * 4 + 4);
                    float2 v0 = make_float2(d[mt][nt][0] + bb0, d[mt][nt][1] + bb1);
                    float2 v1 = make_float2(d[mt][nt][2] + bb0, d[mt][nt][3] + bb1);
                    if (RELU2) {
                        v0.x = fmaxf(v0.x, 0.f); v0.y = fmaxf(v0.y, 0.f);
                        v1.x = fmaxf(v1.x, 0.f); v1.y = fmaxf(v1.y, 0.f);
                    }
                    if (r0 < NN) *(float2*)(out + (size_t)r0 * DD + c) = v0;
                    if (r1 < NN) *(float2*)(out + (size_t)r1 * DD + c) = v1;
                }
            }
        }
    }
#undef RUN_GEMM
}

// ---------------------------------------------------------------------------
// CSR construction (R12-proven: detect -> hist -> scan_block -> add_off -> fill)
// ---------------------------------------------------------------------------
__global__ void detect_kernel(const long long* __restrict__ ei)
{
    const int lane = threadIdx.x & 31;
    int bad = 0;
#pragma unroll
    for (int c = 0; c < 32; c++) {
        long long v = ei[c * 32 + lane];
        bad |= (v < 0 || v >= NN);
    }
    unsigned m = __ballot_sync(0xffffffffu, bad);
    if (lane == 0) g_flag64 = (m == 0u);
}

__global__ void __launch_bounds__(256) hist_kernel(const void* __restrict__ ei_raw)
{
    unsigned e2 = (blockIdx.x * blockDim.x + threadIdx.x) * 2;
    if (e2 >= EE) return;
    int d0, d1;
    if (g_flag64) {
        const longlong2 v = *(const longlong2*)((const long long*)ei_raw + EE + e2);
        d0 = (int)v.x; d1 = (int)v.y;
    } else {
        const int2 v = *(const int2*)((const int*)ei_raw + EE + e2);
        d0 = v.x; d1 = v.y;
    }
    if ((unsigned)d0 < NN) atomicAdd(&g_cnt[d0], 1);
    if ((unsigned)d1 < NN) atomicAdd(&g_cnt[d1], 1);
}

__global__ void __launch_bounds__(256) scan_block_kernel()
{
    __shared__ int s[256];
    int i = blockIdx.x * 256 + threadIdx.x;
    int v = (i < NN) ? g_cnt[i] : 0;
    if (i < NN) g_cnt[i] = 0;       // re-zero for next call
    s[threadIdx.x] = v;
    __syncthreads();
#pragma unroll
    for (int off = 1; off < 256; off <<= 1) {
        int t = (threadIdx.x >= off) ? s[threadIdx.x - off] : 0;
        __syncthreads();
        if (threadIdx.x >= off) s[threadIdx.x] += t;
        __syncthreads();
    }
    if (i < NN) g_rowptr[i] = s[threadIdx.x] - v;
    if (threadIdx.x == 255) g_bsum[blockIdx.x] = s[255];
}

__global__ void __launch_bounds__(256) add_off_kernel()
{
    __shared__ int base_s;
    const int bid = blockIdx.x;
    if (threadIdx.x < 32) {
        int s = 0;
        for (int i = threadIdx.x; i < bid; i += 32) s += g_bsum[i];
#pragma unroll
        for (int off = 16; off; off >>= 1)
            s += __shfl_down_sync(0xffffffffu, s, off);
        if (threadIdx.x == 0) base_s = s;
    }
    __syncthreads();
    int i = bid * 256 + threadIdx.x;
    if (i < NN) {
        int rp = g_rowptr[i] + base_s;
        g_rowptr[i] = rp;
        g_cur[i] = rp;
    }
    if (i == 0) g_rowptr[NN] = EE;
}

__global__ void __launch_bounds__(256) fill_kernel(const void* __restrict__ ei_raw)
{
    unsigned e2 = (blockIdx.x * blockDim.x + threadIdx.x) * 2;
    if (e2 >= EE) return;
    int s0, s1, d0, d1;
    if (g_flag64) {
        const longlong2 sv = *(const longlong2*)((const long long*)ei_raw + e2);
        const longlong2 dv = *(const longlong2*)((const long long*)ei_raw + EE + e2);
        s0 = (int)sv.x; s1 = (int)sv.y;
        d0 = (int)dv.x; d1 = (int)dv.y;
    } else {
        const int2 sv = *(const int2*)((const int*)ei_raw + e2);
        const int2 dv = *(const int2*)((const int*)ei_raw + EE + e2);
        s0 = sv.x; s1 = sv.y;
        d0 = dv.x; d1 = dv.y;
    }
    if ((unsigned)d0 < NN && (unsigned)s0 < NN)
        g_col[atomicAdd(&g_cur[d0], 1)] = s0;
    if ((unsigned)d1 < NN && (unsigned)s1 < NN)
        g_col[atomicAdd(&g_cur[d1], 1)] = s1;
}

// ---------------------------------------------------------------------------
// Launcher
// ---------------------------------------------------------------------------
extern "C" void kernel_launch(void* const* d_in, const int* in_sizes, int n_in,
                              void* d_out, int out_size)
{
    const float* x   = (const float*)d_in[0];
    const void*  ei  = d_in[1];
    const float* W1  = (const float*)d_in[2];
    const float* b1  = (const float*)d_in[3];
    const float* gam = (const float*)d_in[4];
    const float* bet = (const float*)d_in[5];
    const float* bmu = (const float*)d_in[6];
    const float* bva = (const float*)d_in[7];
    const float* W2  = (const float*)d_in[8];
    const float* b2  = (const float*)d_in[9];
    const float* eps = (const float*)d_in[10];
    float*       out = (float*)d_out;

    float* hbuf;
    cudaGetSymbolAddress((void**)&hbuf, g_h);
    float* Abuf;
    cudaGetSymbolAddress((void**)&Abuf, g_A);

    cudaFuncSetAttribute(fused_layer_kernel<1>, cudaFuncAttributeMaxDynamicSharedMemorySize, SMEM_TOTAL);
    cudaFuncSetAttribute(fused_layer_kernel<0>, cudaFuncAttributeMaxDynamicSharedMemorySize, SMEM_TOTAL);

    const int eb2 = (EE / 2 + 255) / 256;          // 1563 (2 edges/thread)
    const int gat_blocks = (NN * 32 + 255) / 256;  // warp per row

    // ---- CSR build (5 launches, R12-proven) ----
    detect_kernel<<<1, 32>>>((const long long*)ei);
    hist_kernel<<<eb2, 256>>>(ei);
    scan_block_kernel<<<NSCAN, 256>>>();
    add_off_kernel<<<NSCAN, 256>>>();
    fill_kernel<<<eb2, 256>>>(ei);

    // ---- 3 layers: gather -> persistent fused MLP ----
    const float* hin = x;
    for (int l = 0; l < LL; ++l) {
        float* hout = (l == LL - 1) ? out : hbuf;

        gather_kernel<<<gat_blocks, 256>>>(hin, eps, l, Abuf);

        if (l < LL - 1) {
            fused_layer_kernel<1><<<PGRID, 256, SMEM_TOTAL>>>(
                Abuf,
                W1 + (size_t)l * DD * DD, b1 + (size_t)l * DD,
                gam + (size_t)l * DD, bet + (size_t)l * DD,
                bmu + (size_t)l * DD, bva + (size_t)l * DD,
                W2 + (size_t)l * DD * DD, b2 + (size_t)l * DD,
                hout);
        } else {
            fused_layer_kernel<0><<<PGRID, 256, SMEM_TOTAL>>>(
                Abuf,
                W1 + (size_t)l * DD * DD, b1 + (size_t)l * DD,
                gam + (size_t)l * DD, bet + (size_t)l * DD,
                bmu + (size_t)l * DD, bva + (size_t)l * DD,
                W2 + (size_t)l * DD * DD, b2 + (size_t)l * DD,
                hout);
        }
        hin = hout;
    }
}